// round 5
// baseline (speedup 1.0000x reference)
#include <cuda_runtime.h>
#include <math.h>
#include <stdint.h>

#define NB    16
#define LSEQ  2048
#define NV    10
#define NPH   19
#define NCLS  190      // 10 tokens * 19 phases
#define NBUCK 3

// ---------------- device scratch (static, allocation-free) ----------------
__device__ __align__(16) uint8_t g_kc[NB * LSEQ];     // class id per key pos
__device__ int    g_tc1[NB * NCLS];                   // first t where rowmax >= -6
__device__ int    g_tc2[NB * NCLS];                   // first t where rowmax >= 94
__device__ float2 g_tab[NV * NPH * NBUCK * NCLS];     // {exp(l-off), exp(l-off)*vv0}

// ---------------- exact-math constants (double) ----------------
__device__ __forceinline__ double d_omega() {
    return 2.0 * 3.14159265358979323846 / 19.0;
}
__device__ __forceinline__ double d_attn_scale() {
    double om  = d_omega();
    double amp = log(10.0) / (cos(om * 0.3) - cos(om * 0.7));
    return 0.5 * amp;   // HEAD_DIM^-0.5 * QK_NORM_SCALE^2 = amp/2
}
__device__ __forceinline__ double d_phi() { return d_omega() * 10.3; }

// s(d) = rmsnorm'd q/k scale, vv0(d) = value component, per token value d
__device__ __forceinline__ void token_consts(int d, double c, double e, double v,
                                             double* sd, double* vv0) {
    double h0 = c - e * (double)(d * d);
    double h1 = -(double)d;
    double r  = 1.0 / sqrt((h0 * h0 + h1 * h1) * 0.5 + 1e-6);
    double hn0 = h0 * r, hn1 = h1 * r;
    *sd  = hn0 / sqrt(hn0 * hn0 * 0.5 + 1e-6);
    *vv0 = hn1 * v;
}

// ---------------- K1: per-batch class ids + first-occurrence -> bucket thresholds ----
__global__ void k_prep(const int* __restrict__ tokens,
                       const float* __restrict__ C, const float* __restrict__ eps) {
    int b = blockIdx.x;
    __shared__ int    fo[NCLS];
    __shared__ double sdv[NV];
    __shared__ double cosm[NPH];
    int tid = threadIdx.x;

    if (tid < NCLS) fo[tid] = 0x7fffffff;
    double c = (double)C[0], e = (double)eps[0];
    if (tid < NV) { double s, dum; token_consts(tid, c, e, 1.0, &s, &dum); sdv[tid] = s; }
    if (tid < NPH) cosm[tid] = cos(d_omega() * (double)tid - d_phi());
    __syncthreads();

    for (int s = tid; s < LSEQ; s += blockDim.x) {
        int tok = tokens[b * LSEQ + s];
        int p   = s % 19;
        int cls = tok + 10 * p;
        g_kc[b * LSEQ + s] = (uint8_t)cls;
        atomicMin(&fo[cls], s);
    }
    __syncthreads();

    if (tid < NCLS) {
        int dt = tid / NPH, tp = tid % NPH;
        double AS = d_attn_scale();
        double sq = sdv[dt];
        int t1 = 0x7fffffff, t2 = 0x7fffffff;
        for (int cc = 0; cc < NCLS; cc++) {
            int d = cc % 10, p = cc / 10;
            int m = tp - p; if (m < 0) m += 19;
            double L = AS * sq * sdv[d] * cosm[m];
            int f = fo[cc];
            if (L >= -6.0) t1 = min(t1, f);
            if (L >=  94.0) t2 = min(t2, f);
        }
        g_tc1[b * NCLS + tid] = t1;
        g_tc2[b * NCLS + tid] = t2;
    }
}

// ---------------- K2: pre-exponentiated class tables ----------------
__global__ void k_table(const float* __restrict__ C, const float* __restrict__ eps,
                        const float* __restrict__ v) {
    int idx = blockIdx.x * blockDim.x + threadIdx.x;
    const int total = NV * NPH * NBUCK * NCLS;
    if (idx >= total) return;
    int cls    = idx % NCLS;
    int rest   = idx / NCLS;
    int bucket = rest % NBUCK; rest /= NBUCK;
    int tp     = rest % NPH;
    int dt     = rest / NPH;

    double c = (double)C[0], e = (double)eps[0], vd = (double)v[0];
    double sdt, dum;  token_consts(dt, c, e, 1.0, &sdt, &dum);
    int d = cls % 10, p = cls / 10;
    double sd, vv0;   token_consts(d, c, e, vd, &sd, &vv0);
    int m = tp - p; if (m < 0) m += 19;
    double L   = d_attn_scale() * sdt * sd * cos(d_omega() * (double)m - d_phi());
    double off = -56.0 + 100.0 * (double)bucket;
    double x   = exp(fmin(L - off, 60.0));   // clamp only hits never-read entries
    g_tab[idx] = make_float2((float)x, (float)(x * vv0));
}

// ---------------- K3: attention via class-table gather + fused epilogue ----------
__global__ void __launch_bounds__(256, 1) k_main(
    const int*   __restrict__ tokens,
    const float* __restrict__ C,        const float* __restrict__ eps,
    const float* __restrict__ o_scale,  const float* __restrict__ g_base,
    const float* __restrict__ g_slope,  const float* __restrict__ carry_amp,
    float* __restrict__ out)
{
    __shared__ uint4  kcs4[LSEQ / 16];          // 2048 bytes of class ids
    __shared__ float2 tbl[8][NCLS];             // per-warp exp tables

    int b    = blockIdx.x >> 7;                 // 128 blocks per batch
    int j    = blockIdx.x & 127;
    int w    = threadIdx.x >> 5;
    int lane = threadIdx.x & 31;

    if (threadIdx.x < LSEQ / 16)
        kcs4[threadIdx.x] = ((const uint4*)(g_kc + b * LSEQ))[threadIdx.x];
    __syncthreads();

    const uint32_t* kc32 = (const uint32_t*)kcs4;

    float c  = C[0],       ee = eps[0],     osc = o_scale[0];
    float ga = g_base[0],  gc = g_slope[0], ca  = carry_amp[0];

    int trow0 = j * 8 + w;                      // 0..1023
    #pragma unroll 1
    for (int rr = 0; rr < 2; rr++) {
        int t  = (rr == 0) ? trow0 : (LSEQ - 1 - trow0);
        int dt = tokens[b * LSEQ + t];
        int tp = t % 19;
        int idx190 = dt * NPH + tp;
        int bucket = (t >= g_tc1[b * NCLS + idx190]) + (t >= g_tc2[b * NCLS + idx190]);
        const float2* Tg = g_tab + (idx190 * NBUCK + bucket) * NCLS;
        for (int i = lane; i < NCLS; i += 32) tbl[w][i] = Tg[i];
        __syncwarp();

        float den0 = 0.f, num0 = 0.f, den1 = 0.f, num1 = 0.f;
        for (int s0 = 0; s0 <= t; s0 += 128) {
            uint32_t k4 = kc32[(s0 >> 2) + lane];
            int sBase = s0 + lane * 4;
            float2 a0 = tbl[w][ k4        & 255];
            float2 a1 = tbl[w][(k4 >>  8) & 255];
            float2 a2 = tbl[w][(k4 >> 16) & 255];
            float2 a3 = tbl[w][ k4 >> 24       ];
            if (sBase     <= t) { den0 += a0.x; num0 += a0.y; }
            if (sBase + 1 <= t) { den1 += a1.x; num1 += a1.y; }
            if (sBase + 2 <= t) { den0 += a2.x; num0 += a2.y; }
            if (sBase + 3 <= t) { den1 += a3.x; num1 += a3.y; }
        }
        float den = den0 + den1, num = num0 + num1;
        #pragma unroll
        for (int o = 16; o; o >>= 1) {
            den += __shfl_xor_sync(0xffffffffu, den, o);
            num += __shfl_xor_sync(0xffffffffu, num, o);
        }
        float attn = num / den;

        // fused epilogue (exactly mirrors reference fp32 math)
        float h0 = c - ee * (float)(dt * dt);
        float h1 = -(float)dt + osc * attn;
        float r  = rsqrtf((h0 * h0 + h1 * h1) * 0.5f + 1e-6f);
        float hn0 = h0 * r, hn1 = h1 * r;
        float g0  = hn0 * ga + hn1 * gc;
        float g1  = hn0 * (ga - gc / c) + hn1 * gc;
        float carry = ca * (fmaxf(g1, 0.f) * hn0 - fmaxf(g0, 0.f) * hn0);
        float h1c = h1 + carry;
        float r2  = rsqrtf((h0 * h0 + h1c * h1c) * 0.5f + 1e-6f);
        const float inv_cn = 0.7071067811865475f;          // 1/sqrt(MODEL_DIM)
        float a0o = h0  * r2 * (0.1f * c * inv_cn);
        float a1o = h1c * r2 * (-c * 0.02f * inv_cn);      // -c/(50*sqrt2)
        if (lane < NV) {
            float t0 = c - ee * (float)(lane * lane);
            float t1v = -(float)lane;
            out[(b * LSEQ + t) * NV + lane] = a0o * t0 + a1o * t1v;
        }
        __syncwarp();   // protect tbl[w] before it is rebuilt for row 2
    }
}

// ---------------- launch ----------------
extern "C" void kernel_launch(void* const* d_in, const int* in_sizes, int n_in,
                              void* d_out, int out_size) {
    const int*   tokens    = (const int*)  d_in[0];
    const float* C         = (const float*)d_in[1];
    const float* eps       = (const float*)d_in[2];
    const float* v         = (const float*)d_in[3];
    const float* o_scale   = (const float*)d_in[4];
    const float* g_base    = (const float*)d_in[5];
    const float* g_slope   = (const float*)d_in[6];
    const float* carry_amp = (const float*)d_in[7];
    float* out = (float*)d_out;

    k_prep<<<NB, 256>>>(tokens, C, eps);
    const int total = NV * NPH * NBUCK * NCLS;
    k_table<<<(total + 255) / 256, 256>>>(C, eps, v);
    k_main<<<NB * 128, 256>>>(tokens, C, eps, o_scale, g_base, g_slope, carry_amp, out);
}

// round 6
// speedup vs baseline: 4.0893x; 4.0893x over previous
#include <cuda_runtime.h>
#include <math.h>
#include <stdint.h>

#define NB     16
#define LSEQ   2048
#define NV     10
#define NPH    19
#define NCLS   190       // 10 tokens * 19 phases
#define NCLSP  192       // padded (2 zero classes)
#define NBUCK  3
#define NCHUNK 16
#define CHUNK  128

// ---------------- device scratch (static, allocation-free) ----------------
__device__ float    g_sduF[NV];        // per-token q/k scale s(d)
__device__ float    g_vv0F[NV];        // per-token value vv0(d) (includes *v)
__device__ float    g_cosmF[NPH];      // cos(omega*m - phi)
__device__ float    g_ASF;             // ATTN_SCALE
__device__ int      g_tc1[NB * NCLS];  // first t where rowmax >= -6
__device__ int      g_tc2[NB * NCLS];  // first t where rowmax >= 94
__device__ uint16_t g_cbase[NB * NCHUNK * NCLSP];           // exclusive chunk prefix counts
__device__ __align__(16) float2 g_tab[NCLS * NBUCK * NCLSP]; // {e, e*vv0} per (q,bucket,cls)

// ---------------- exact-math constants (double, used once) ----------------
__device__ __forceinline__ double d_omega() {
    return 2.0 * 3.14159265358979323846 / 19.0;
}
__device__ __forceinline__ double d_attn_scale() {
    double om  = d_omega();
    double amp = log(10.0) / (cos(om * 0.3) - cos(om * 0.7));
    return 0.5 * amp;   // HEAD_DIM^-0.5 * QK_NORM_SCALE^2 = amp/2
}
__device__ __forceinline__ double d_phi() { return d_omega() * 10.3; }

__device__ __forceinline__ void token_consts(int d, double c, double e, double v,
                                             double* sd, double* vv0) {
    double h0 = c - e * (double)(d * d);
    double h1 = -(double)d;
    double r  = 1.0 / sqrt((h0 * h0 + h1 * h1) * 0.5 + 1e-6);
    double hn0 = h0 * r, hn1 = h1 * r;
    *sd  = hn0 / sqrt(hn0 * hn0 * 0.5 + 1e-6);
    *vv0 = hn1 * v;
}

// ---------------- K1: per-batch histograms, prefix bases, bucket thresholds ----
__global__ void k_prep(const int* __restrict__ tokens,
                       const float* __restrict__ C, const float* __restrict__ eps,
                       const float* __restrict__ v) {
    int b   = blockIdx.x;
    int tid = threadIdx.x;
    __shared__ int   hist[NCHUNK][NCLSP];
    __shared__ int   fo[NCLS];
    __shared__ float sdf[NV], cmf[NPH];
    __shared__ float asf_sh;

    for (int i = tid; i < NCHUNK * NCLSP; i += 256) ((int*)hist)[i] = 0;
    if (tid < NCLS) fo[tid] = 0x7fffffff;

    double c = (double)C[0], e = (double)eps[0], vd = (double)v[0];
    if (tid < NV) {
        double s, w; token_consts(tid, c, e, vd, &s, &w);
        sdf[tid] = (float)s;
        if (b == 0) { g_sduF[tid] = (float)s; g_vv0F[tid] = (float)w; }
    }
    if (tid < NPH) {
        double cm = cos(d_omega() * (double)tid - d_phi());
        cmf[tid] = (float)cm;
        if (b == 0) g_cosmF[tid] = (float)cm;
    }
    if (tid == 0) {
        float A = (float)d_attn_scale();
        asf_sh = A;
        if (b == 0) g_ASF = A;
    }
    __syncthreads();

    for (int s = tid; s < LSEQ; s += 256) {
        int tok = tokens[b * LSEQ + s];
        int cls = tok + 10 * (s % NPH);
        atomicAdd(&hist[s >> 7][cls], 1);
        atomicMin(&fo[cls], s);
    }
    __syncthreads();

    if (tid < NCLS) {
        float sq  = sdf[tid / NPH] * asf_sh;
        int   tpq = tid % NPH;
        int t1 = 0x7fffffff, t2 = 0x7fffffff;
        for (int p = 0; p < NPH; p++) {
            int m = tpq - p; if (m < 0) m += NPH;
            float cv = cmf[m];
            #pragma unroll
            for (int d = 0; d < NV; d++) {
                float L = sq * sdf[d] * cv;
                int f = fo[d + 10 * p];
                if (L >= -6.0f) t1 = min(t1, f);
                if (L >= 94.0f) t2 = min(t2, f);
            }
        }
        g_tc1[b * NCLS + tid] = t1;
        g_tc2[b * NCLS + tid] = t2;
    }
    if (tid < NCLSP) {
        int run = 0;
        for (int ch = 0; ch < NCHUNK; ch++) {
            g_cbase[(b * NCHUNK + ch) * NCLSP + tid] = (uint16_t)run;
            run += hist[ch][tid];
        }
    }
}

// ---------------- K2: pre-exponentiated class tables (all float) ----------------
__global__ void k_table() {
    int idx = blockIdx.x * blockDim.x + threadIdx.x;
    const int total = NCLS * NBUCK * NCLSP;
    if (idx >= total) return;
    int cls    = idx % NCLSP;
    int rest   = idx / NCLSP;
    int bucket = rest % NBUCK;
    int q      = rest / NBUCK;     // query class idx190
    float2 r = make_float2(0.f, 0.f);
    if (cls < NCLS) {
        int dt = q / NPH, tp = q % NPH;
        int d  = cls % 10, p = cls / 10;
        int m  = tp - p; if (m < 0) m += NPH;
        float L   = g_ASF * g_sduF[dt] * g_sduF[d] * g_cosmF[m];
        float off = -56.0f + 100.0f * (float)bucket;
        float x   = expf(fminf(L - off, 60.0f));   // clamp only hits never-read entries
        r = make_float2(x, x * g_vv0F[d]);
    }
    g_tab[idx] = r;
}

// ---------------- K3: cumulative-histogram softmax + fused epilogue ----------
__global__ void __launch_bounds__(256) k_main(
    const int*   __restrict__ tokens,
    const float* __restrict__ C,        const float* __restrict__ eps,
    const float* __restrict__ o_scale,  const float* __restrict__ g_base,
    const float* __restrict__ g_slope,  const float* __restrict__ carry_amp,
    float* __restrict__ out)
{
    extern __shared__ uint16_t cnt_sh[];   // [CHUNK][NCLSP] inclusive cumulative counts
    __shared__ int tok_sh[CHUNK];

    int b   = blockIdx.x >> 4;
    int ch  = blockIdx.x & 15;
    int tid = threadIdx.x;
    int T0  = ch * CHUNK;

    if (tid < CHUNK) tok_sh[tid] = tokens[b * LSEQ + T0 + tid];
    __syncthreads();

    // Build cumulative per-class counts: thread = class, serial walk over 128 rows.
    if (tid < NCLSP) {
        int cnt = (int)g_cbase[(b * NCHUNK + ch) * NCLSP + tid];
        int ph  = T0 % NPH;
        #pragma unroll 4
        for (int p = 0; p < CHUNK; p++) {
            int cls = tok_sh[p] + 10 * ph;
            cnt += (cls == tid);
            cnt_sh[p * NCLSP + tid] = (uint16_t)cnt;
            ph++; if (ph == NPH) ph = 0;
        }
    }
    __syncthreads();

    float c  = C[0],      ee = eps[0],     osc = o_scale[0];
    float ga = g_base[0], gc = g_slope[0], ca  = carry_amp[0];

    int w = tid >> 5, lane = tid & 31;
    const uint32_t* cnt32 = (const uint32_t*)cnt_sh;

    // Preload bucket thresholds for this warp's 16 rows (lanes 0-15: tc1, 16-31: tc2)
    int myr  = lane & 15;
    int myt  = T0 + w * 16 + myr;
    int mydt = tok_sh[w * 16 + myr];
    int myq  = mydt * NPH + (myt % NPH);
    const int* tcp = (lane < 16) ? g_tc1 : g_tc2;
    int tcv = tcp[b * NCLS + myq];

    #pragma unroll 4
    for (int rr = 0; rr < 16; rr++) {
        int r  = w * 16 + rr;
        int t  = T0 + r;
        int dt = tok_sh[r];
        int tp = t % NPH;
        int q  = dt * NPH + tp;
        int tc1v = __shfl_sync(0xffffffffu, tcv, rr);
        int tc2v = __shfl_sync(0xffffffffu, tcv, rr + 16);
        int bucket = (t >= tc1v) + (t >= tc2v);

        const float4* Tb = (const float4*)(g_tab + (q * NBUCK + bucket) * NCLSP) + lane * 3;
        float4 e0 = __ldg(Tb + 0);
        float4 e1 = __ldg(Tb + 1);
        float4 e2 = __ldg(Tb + 2);

        int base = r * (NCLSP / 2) + lane * 3;        // uint32 index (conflict-free: 3 coprime 32)
        uint32_t u0 = cnt32[base], u1 = cnt32[base + 1], u2 = cnt32[base + 2];
        float c0 = (float)(u0 & 0xffff), c1 = (float)(u0 >> 16);
        float c2 = (float)(u1 & 0xffff), c3 = (float)(u1 >> 16);
        float c4 = (float)(u2 & 0xffff), c5 = (float)(u2 >> 16);

        float den = c0 * e0.x + c1 * e0.z + c2 * e1.x + c3 * e1.z + c4 * e2.x + c5 * e2.z;
        float num = c0 * e0.y + c1 * e0.w + c2 * e1.y + c3 * e1.w + c4 * e2.y + c5 * e2.w;

        #pragma unroll
        for (int o = 16; o; o >>= 1) {
            den += __shfl_xor_sync(0xffffffffu, den, o);
            num += __shfl_xor_sync(0xffffffffu, num, o);
        }
        float attn = num / den;

        // fused epilogue (mirrors reference fp32 math exactly)
        float h0 = c - ee * (float)(dt * dt);
        float h1 = -(float)dt + osc * attn;
        float rn = rsqrtf((h0 * h0 + h1 * h1) * 0.5f + 1e-6f);
        float hn0 = h0 * rn, hn1 = h1 * rn;
        float g0  = hn0 * ga + hn1 * gc;
        float g1  = hn0 * (ga - gc / c) + hn1 * gc;
        float carry = ca * (fmaxf(g1, 0.f) * hn0 - fmaxf(g0, 0.f) * hn0);
        float h1c = h1 + carry;
        float r2  = rsqrtf((h0 * h0 + h1c * h1c) * 0.5f + 1e-6f);
        const float inv_cn = 0.7071067811865475f;      // 1/sqrt(MODEL_DIM)
        float a0o = h0  * r2 * (0.1f * c * inv_cn);
        float a1o = h1c * r2 * (-c * 0.02f * inv_cn);  // -c/(50*sqrt2)
        if (lane < NV) {
            float t0  = c - ee * (float)(lane * lane);
            float t1v = -(float)lane;
            out[(b * LSEQ + t) * NV + lane] = a0o * t0 + a1o * t1v;
        }
    }
}

// ---------------- launch ----------------
extern "C" void kernel_launch(void* const* d_in, const int* in_sizes, int n_in,
                              void* d_out, int out_size) {
    const int*   tokens    = (const int*)  d_in[0];
    const float* C         = (const float*)d_in[1];
    const float* eps       = (const float*)d_in[2];
    const float* v         = (const float*)d_in[3];
    const float* o_scale   = (const float*)d_in[4];
    const float* g_base    = (const float*)d_in[5];
    const float* g_slope   = (const float*)d_in[6];
    const float* carry_amp = (const float*)d_in[7];
    float* out = (float*)d_out;

    const int smem = CHUNK * NCLSP * (int)sizeof(uint16_t);   // 49152
    cudaFuncSetAttribute(k_main, cudaFuncAttributeMaxDynamicSharedMemorySize, smem);

    k_prep<<<NB, 256>>>(tokens, C, eps, v);
    const int total = NCLS * NBUCK * NCLSP;
    k_table<<<(total + 255) / 256, 256>>>();
    k_main<<<NB * NCHUNK, 256, smem>>>(tokens, C, eps, o_scale, g_base, g_slope,
                                       carry_amp, out);
}